// round 16
// baseline (speedup 1.0000x reference)
#include <cuda_runtime.h>
#include <math.h>

// Problem constants
#define G2   64
#define Hh   64
#define Aa   1024
#define Ss   32
#define Pp   4096
#define Bb   2048
#define BMAX 512   // occupancy-count bucket range for ectx

typedef unsigned long long ull;

// -------- packed f32x2 helpers --------
__device__ __forceinline__ ull pk2(float lo, float hi) {
    ull r; asm("mov.b64 %0, {%1,%2};" : "=l"(r) : "f"(lo), "f"(hi)); return r;
}
__device__ __forceinline__ void upk2(ull v, float& lo, float& hi) {
    asm("mov.b64 {%0,%1}, %2;" : "=f"(lo), "=f"(hi) : "l"(v));
}
__device__ __forceinline__ ull ffma2(ull a, ull b, ull c) {
    ull d; asm("fma.rn.f32x2 %0, %1, %2, %3;" : "=l"(d) : "l"(a), "l"(b), "l"(c));
    return d;
}

// -------- device scratch (no allocations allowed) --------
__device__ float g_occ[Bb * G2];
__device__ float g_c[Bb * Aa];
__device__ float g_ctx[Bb];
__device__ float g_wc[70 * Aa];
__device__ float g_y[Bb * Aa];
__device__ float g_sum[Aa];
__device__ float g_sumsq[Aa];

// ---------------------------------------------------------------------------
// NODE 1: c = h@W_dec + b_dec + b_enc (4-col x 8-row register tiles),
//         PLUS zero g_wc/g_sum/g_sumsq.  grid (2, 256) x 128 thr.
__global__ __launch_bounds__(128) void prep_kernel(const float* __restrict__ h,
                                                   const float* __restrict__ Wd,
                                                   const float* __restrict__ bd,
                                                   const float* __restrict__ be) {
    {
        int gidx = (blockIdx.y * 2 + blockIdx.x) * 128 + threadIdx.x;
        const float4 z = make_float4(0.f, 0.f, 0.f, 0.f);
        if (gidx < 17920) {
            reinterpret_cast<float4*>(g_wc)[gidx] = z;
        } else if (gidx < 17920 + 256) {
            reinterpret_cast<float4*>(g_sum)[gidx - 17920] = z;
        } else if (gidx < 17920 + 512) {
            reinterpret_cast<float4*>(g_sumsq)[gidx - 17920 - 256] = z;
        }
    }

    int col0 = blockIdx.x * 512 + threadIdx.x * 4;
    int b0   = blockIdx.y * 8;
    __shared__ __align__(16) float hp[Hh * 8];   // hp[k*8 + bl]
    for (int idx = threadIdx.x; idx < 8 * Hh; idx += 128) {
        int k = idx >> 3, bl = idx & 7;
        hp[idx] = h[(b0 + bl) * Hh + k];
    }
    __syncthreads();

    ull acc[16];   // acc[c*4+p]: column c, row-pair p (rows 2p,2p+1)
#pragma unroll
    for (int i = 0; i < 16; i++) acc[i] = 0ull;

    const ulonglong2* hu = reinterpret_cast<const ulonglong2*>(hp);
#pragma unroll 4
    for (int k = 0; k < Hh; k += 4) {
        float4 wv[4];
#pragma unroll
        for (int i = 0; i < 4; i++)
            wv[i] = *reinterpret_cast<const float4*>(Wd + (size_t)(k + i) * Aa + col0);
#pragma unroll
        for (int rr = 0; rr < 4; rr++) {
            ulonglong2 u01 = hu[(k + rr) * 2];
            ulonglong2 u23 = hu[(k + rr) * 2 + 1];
            ull up[4] = { u01.x, u01.y, u23.x, u23.y };
            ull ww[4] = { pk2(wv[rr].x, wv[rr].x), pk2(wv[rr].y, wv[rr].y),
                          pk2(wv[rr].z, wv[rr].z), pk2(wv[rr].w, wv[rr].w) };
#pragma unroll
            for (int c = 0; c < 4; c++)
#pragma unroll
                for (int p = 0; p < 4; p++)
                    acc[c * 4 + p] = ffma2(up[p], ww[c], acc[c * 4 + p]);
        }
    }
    float4 bias;
    {
        float4 b1 = *reinterpret_cast<const float4*>(bd + col0);
        float4 b2 = *reinterpret_cast<const float4*>(be + col0);
        bias = make_float4(b1.x + b2.x, b1.y + b2.y, b1.z + b2.z, b1.w + b2.w);
    }
#pragma unroll
    for (int p = 0; p < 4; p++) {
        float v[2][4];
#pragma unroll
        for (int c = 0; c < 4; c++) {
            float lo, hi; upk2(acc[c * 4 + p], lo, hi);
            v[0][c] = lo; v[1][c] = hi;
        }
#pragma unroll
        for (int hh = 0; hh < 2; hh++) {
            float4 o = make_float4(v[hh][0] + bias.x, v[hh][1] + bias.y,
                                   v[hh][2] + bias.z, v[hh][3] + bias.w);
            *reinterpret_cast<float4*>(g_c + (size_t)(b0 + 2 * p + hh) * Aa + col0) = o;
        }
    }
}

// ---------------------------------------------------------------------------
// NODE 2: fat kernel — blocks [0,256): occupancy (plain stores, own region);
//         [256,768): Wc atomics (needs g_wc zeroed by prep).
__global__ __launch_bounds__(256) void occwc_kernel(const float* __restrict__ end_pos,
                                                    const float* __restrict__ scene,
                                                    const float* __restrict__ Wo,
                                                    const float* __restrict__ bo,
                                                    const float* __restrict__ Wm) {
    if (blockIdx.x < 256) {
        int grp = blockIdx.x & 7;
        int s   = blockIdx.x >> 3;
        int pedbase = s * 64 + grp * 8;

        __shared__ int bins[8][G2];
        __shared__ float4 boxsh[8];
        for (int i = threadIdx.x; i < 8 * G2; i += 256) ((int*)bins)[i] = 0;
        if (threadIdx.x < 8) {
            float ex = end_pos[(pedbase + threadIdx.x) * 2 + 0];
            float ey = end_pos[(pedbase + threadIdx.x) * 2 + 1];
            boxsh[threadIdx.x] = make_float4(ex - 1.0f, ey + 1.0f, ex + 1.0f, ey - 1.0f);
        }
        __syncthreads();

        float4 bx[8];
#pragma unroll
        for (int j = 0; j < 8; j++) bx[j] = boxsh[j];

        const float2* sc = reinterpret_cast<const float2*>(scene) + (size_t)s * Pp;
        for (int p = threadIdx.x; p < Pp; p += 256) {
            float2 q = sc[p];
#pragma unroll
            for (int j = 0; j < 8; j++) {
                bool in = (q.x < bx[j].z) && (q.x > bx[j].x) &&
                          (q.y < bx[j].y) && (q.y > bx[j].w);
                if (in) {
                    float cx = floorf(((q.x - bx[j].x) / 2.0f) * 8.0f);
                    float cy = floorf(((bx[j].y - q.y) / 2.0f) * 8.0f);
                    int cell = (int)(cx + cy * 8.0f);
                    if (cell >= 0 && cell < G2) {
                        atomicAdd(&bins[j][cell], 1);
                    } else {
                        long flat = (long)(pedbase + j) * G2 + cell;
                        if (flat >= 0 && flat < (long)Bb * G2)
                            atomicAdd(&g_occ[flat], 1.0f);   // rare bleed, exact int adds
                    }
                }
            }
        }
        __syncthreads();
        // own region: plain store (no zeroing pass needed)
        for (int i = threadIdx.x; i < 8 * G2; i += 256)
            g_occ[pedbase * G2 + i] = (float)((int*)bins)[i];
    } else {
        int wcb = blockIdx.x - 256;          // 0..511
        int a   = (wcb & 3) * 256 + threadIdx.x;
        int r0  = ((wcb >> 2) & 3) * 18;
        int k0  = (wcb >> 4) * 32;
        __shared__ __align__(16) float ws[9 * 32 * 2];

        for (int idx = threadIdx.x; idx < 9 * 32; idx += 256) {
            int p = idx >> 5, k = idx & 31;
            int r = r0 + 2 * p;
            float v0 = 0.f, v1 = 0.f;
            if (r < 69)       v0 = Wo[r * Aa + k0 + k];
            else if (r == 69) v0 = bo[k0 + k];
            if (r + 1 < 69)       v1 = Wo[(r + 1) * Aa + k0 + k];
            else if (r + 1 == 69) v1 = bo[k0 + k];
            ws[idx * 2]     = v0;
            ws[idx * 2 + 1] = v1;
        }
        __syncthreads();

        ull acc[9];
#pragma unroll
        for (int p = 0; p < 9; p++) acc[p] = 0ull;

        const ulonglong2* wsu = reinterpret_cast<const ulonglong2*>(ws);
#pragma unroll 2
        for (int k = 0; k < 32; k += 2) {
            float w0 = Wm[(size_t)(k0 + k) * Aa + a];
            float w1 = Wm[(size_t)(k0 + k + 1) * Aa + a];
            ull ww0 = pk2(w0, w0), ww1 = pk2(w1, w1);
#pragma unroll
            for (int p = 0; p < 9; p++) {
                ulonglong2 v = wsu[p * 16 + (k >> 1)];
                acc[p] = ffma2(v.x, ww0, acc[p]);
                acc[p] = ffma2(v.y, ww1, acc[p]);
            }
        }
#pragma unroll
        for (int p = 0; p < 9; p++) {
            int r = r0 + 2 * p;
            float lo, hi; upk2(acc[p], lo, hi);
            if (r < 70)     atomicAdd(&g_wc[r * Aa + a], lo);
            if (r + 1 < 70) atomicAdd(&g_wc[(r + 1) * Aa + a], hi);
        }
    }
}

// ---------------------------------------------------------------------------
// NODE 3: ectx via activation-threshold bucketing (proven R14 code).
__global__ __launch_bounds__(128) void ectx_kernel(const float* __restrict__ We,
                                                   const float* __restrict__ wf) {
    __shared__ float Ad[BMAX], Cd[BMAX];
    __shared__ float sA[128], sC[128];
    __shared__ float redm[4], reds[4], redc[4];

    const int b   = blockIdx.x;
    const int tid = threadIdx.x;
    const float* crow = g_c + (size_t)b * Aa;

    for (int i = tid; i < BMAX; i += 128) { Ad[i] = 0.f; Cd[i] = 0.f; }
    __syncthreads();

    float A0 = 0.f, C0 = 0.f;
    for (int a = tid; a < Aa; a += 128) {
        float we = We[a], w = wf[a], c = crow[a];
        float wewf = we * w, cwf = c * w;
        if (we > 0.f) {
            float tau = __fdividef(-c, we);          // active for t > tau
            if (tau < 0.f) { A0 += wewf; C0 += cwf; }
            else if (tau < (float)(BMAX - 1)) {
                int t0 = (int)tau + 1;
                atomicAdd(&Ad[t0], wewf);
                atomicAdd(&Cd[t0], cwf);
            }
        } else if (we < 0.f) {
            float tau = __fdividef(-c, we);          // active for t < tau
            if (tau >= (float)(BMAX - 1)) { A0 += wewf; C0 += cwf; }
            else if (tau > 0.f) {
                A0 += wewf; C0 += cwf;
                int t1 = (int)ceilf(tau);
                atomicAdd(&Ad[t1], -wewf);
                atomicAdd(&Cd[t1], -cwf);
            }
        } else if (c > 0.f) {
            C0 += cwf;
        }
    }
#pragma unroll
    for (int off = 16; off >= 1; off >>= 1) {
        A0 += __shfl_xor_sync(0xffffffffu, A0, off);
        C0 += __shfl_xor_sync(0xffffffffu, C0, off);
    }
    if ((tid & 31) == 0) { atomicAdd(&Ad[0], A0); atomicAdd(&Cd[0], C0); }
    __syncthreads();

    int base = tid * 4;
    float pa0 = Ad[base], pa1 = Ad[base + 1], pa2 = Ad[base + 2], pa3 = Ad[base + 3];
    float pc0 = Cd[base], pc1 = Cd[base + 1], pc2 = Cd[base + 2], pc3 = Cd[base + 3];
    pa1 += pa0; pa2 += pa1; pa3 += pa2;
    pc1 += pc0; pc2 += pc1; pc3 += pc2;
    sA[tid] = pa3; sC[tid] = pc3;
    __syncthreads();
    for (int off = 1; off < 128; off <<= 1) {
        float va = (tid >= off) ? sA[tid - off] : 0.f;
        float vc = (tid >= off) ? sC[tid - off] : 0.f;
        __syncthreads();
        sA[tid] += va; sC[tid] += vc;
        __syncthreads();
    }
    float offA = sA[tid] - pa3, offC = sC[tid] - pc3;
    Ad[base] = pa0 + offA; Ad[base + 1] = pa1 + offA;
    Ad[base + 2] = pa2 + offA; Ad[base + 3] = pa3 + offA;
    Cd[base] = pc0 + offC; Cd[base + 1] = pc1 + offC;
    Cd[base + 2] = pc2 + offC; Cd[base + 3] = pc3 + offC;
    __syncthreads();

    float e = -1e30f, ogv = 0.f;
    if (tid < G2) {
        ogv = g_occ[b * G2 + tid];
        int t = (int)ogv;
        if (t < BMAX) {
            e = Ad[t] * ogv + Cd[t];
        } else {
            e = 0.f;
            for (int a = 0; a < Aa; a++)
                e = fmaf(fmaxf(fmaf(ogv, We[a], crow[a]), 0.f), wf[a], e);
        }
    }
    int warp = tid >> 5;
    float m = e;
#pragma unroll
    for (int off = 16; off >= 1; off >>= 1)
        m = fmaxf(m, __shfl_xor_sync(0xffffffffu, m, off));
    if ((tid & 31) == 0) redm[warp] = m;
    __syncthreads();
    m = fmaxf(fmaxf(redm[0], redm[1]), fmaxf(redm[2], redm[3]));

    float ex = __expf(e - m);
    float s = ex, cx = ex * ogv;
#pragma unroll
    for (int off = 16; off >= 1; off >>= 1) {
        s  += __shfl_xor_sync(0xffffffffu, s, off);
        cx += __shfl_xor_sync(0xffffffffu, cx, off);
    }
    if ((tid & 31) == 0) { reds[warp] = s; redc[warp] = cx; }
    __syncthreads();
    if (tid == 0)
        g_ctx[b] = (redc[0] + redc[1] + redc[2] + redc[3]) /
                   (reds[0] + reds[1] + reds[2] + reds[3]);
}

// ---------------------------------------------------------------------------
// NODE 4: y = u@Wc + bias (4-col x 8-row tiles), stats atomics.
//         grid (2, 256) x 128 thr.
__global__ __launch_bounds__(128) void y_kernel(const float* __restrict__ h,
                                                const float* __restrict__ ep,
                                                const float* __restrict__ rp,
                                                const float* __restrict__ bm) {
    int col0 = blockIdx.x * 512 + threadIdx.x * 4;
    int b0   = blockIdx.y * 8;
    __shared__ __align__(16) float us[69 * 8];   // us[r*8 + bl]
    for (int idx = threadIdx.x; idx < 69 * 8; idx += 128) {
        int r = idx >> 3, bl = idx & 7;
        int b = b0 + bl;
        float v;
        if (r == 0)      v = g_ctx[b];
        else if (r < 65) v = h[b * Hh + (r - 1)];
        else if (r < 67) v = ep[b * 2 + (r - 65)];
        else             v = rp[b * 2 + (r - 67)];
        us[idx] = v;
    }
    __syncthreads();

    ull acc[16];   // acc[c*4+p]
#pragma unroll
    for (int i = 0; i < 16; i++) acc[i] = 0ull;

    const ulonglong2* usu = reinterpret_cast<const ulonglong2*>(us);
    const float* wbase = g_wc + col0;
    for (int r = 0; r < 68; r += 4) {
        float4 wv[4];
#pragma unroll
        for (int i = 0; i < 4; i++)
            wv[i] = *reinterpret_cast<const float4*>(wbase + (size_t)(r + i) * Aa);
#pragma unroll
        for (int rr = 0; rr < 4; rr++) {
            ulonglong2 u01 = usu[(r + rr) * 2];
            ulonglong2 u23 = usu[(r + rr) * 2 + 1];
            ull up[4] = { u01.x, u01.y, u23.x, u23.y };
            ull ww[4] = { pk2(wv[rr].x, wv[rr].x), pk2(wv[rr].y, wv[rr].y),
                          pk2(wv[rr].z, wv[rr].z), pk2(wv[rr].w, wv[rr].w) };
#pragma unroll
            for (int c = 0; c < 4; c++)
#pragma unroll
                for (int p = 0; p < 4; p++)
                    acc[c * 4 + p] = ffma2(up[p], ww[c], acc[c * 4 + p]);
        }
    }
    {   // tail r = 68
        float4 wv = *reinterpret_cast<const float4*>(wbase + (size_t)68 * Aa);
        ulonglong2 u01 = usu[68 * 2];
        ulonglong2 u23 = usu[68 * 2 + 1];
        ull up[4] = { u01.x, u01.y, u23.x, u23.y };
        ull ww[4] = { pk2(wv.x, wv.x), pk2(wv.y, wv.y),
                      pk2(wv.z, wv.z), pk2(wv.w, wv.w) };
#pragma unroll
        for (int c = 0; c < 4; c++)
#pragma unroll
            for (int p = 0; p < 4; p++)
                acc[c * 4 + p] = ffma2(up[p], ww[c], acc[c * 4 + p]);
    }

    float4 bias;
    {
        float4 b1 = *reinterpret_cast<const float4*>(wbase + (size_t)69 * Aa);
        float4 b2 = *reinterpret_cast<const float4*>(bm + col0);
        bias = make_float4(b1.x + b2.x, b1.y + b2.y, b1.z + b2.z, b1.w + b2.w);
    }
    float4 s  = make_float4(0.f, 0.f, 0.f, 0.f);
    float4 s2 = make_float4(0.f, 0.f, 0.f, 0.f);
#pragma unroll
    for (int p = 0; p < 4; p++) {
        float v[2][4];
#pragma unroll
        for (int c = 0; c < 4; c++) {
            float lo, hi; upk2(acc[c * 4 + p], lo, hi);
            v[0][c] = lo; v[1][c] = hi;
        }
#pragma unroll
        for (int hh = 0; hh < 2; hh++) {
            float4 o = make_float4(v[hh][0] + bias.x, v[hh][1] + bias.y,
                                   v[hh][2] + bias.z, v[hh][3] + bias.w);
            *reinterpret_cast<float4*>(g_y + (size_t)(b0 + 2 * p + hh) * Aa + col0) = o;
            s.x += o.x; s.y += o.y; s.z += o.z; s.w += o.w;
            s2.x = fmaf(o.x, o.x, s2.x); s2.y = fmaf(o.y, o.y, s2.y);
            s2.z = fmaf(o.z, o.z, s2.z); s2.w = fmaf(o.w, o.w, s2.w);
        }
    }
    atomicAdd(&g_sum[col0 + 0], s.x);
    atomicAdd(&g_sum[col0 + 1], s.y);
    atomicAdd(&g_sum[col0 + 2], s.z);
    atomicAdd(&g_sum[col0 + 3], s.w);
    atomicAdd(&g_sumsq[col0 + 0], s2.x);
    atomicAdd(&g_sumsq[col0 + 1], s2.y);
    atomicAdd(&g_sumsq[col0 + 2], s2.z);
    atomicAdd(&g_sumsq[col0 + 3], s2.w);
}

// ---------------------------------------------------------------------------
// NODE 5: out = relu(layernorm_batchdim(y)), stats recomputed inline.
__global__ __launch_bounds__(256) void finalize_kernel(const float* __restrict__ gamma,
                                                       const float* __restrict__ beta,
                                                       float* __restrict__ out) {
    int idx = blockIdx.x * blockDim.x + threadIdx.x;
    const int n = Bb * Aa / 4;
    if (idx >= n) return;
    int a = (idx * 4) & (Aa - 1);
    float4 v  = reinterpret_cast<const float4*>(g_y)[idx];
    float4 s4 = *reinterpret_cast<const float4*>(&g_sum[a]);
    float4 q4 = *reinterpret_cast<const float4*>(&g_sumsq[a]);
    float4 gm = *reinterpret_cast<const float4*>(&gamma[a]);
    float4 bt = *reinterpret_cast<const float4*>(&beta[a]);
    const float inv = 1.0f / (float)Bb;
    float4 o;
    {
        float mu = s4.x * inv, var = q4.x * inv - mu * mu;
        float sc = gm.x * rsqrtf(var + 1e-5f);
        o.x = fmaxf(fmaf(v.x, sc, bt.x - mu * sc), 0.f);
    }
    {
        float mu = s4.y * inv, var = q4.y * inv - mu * mu;
        float sc = gm.y * rsqrtf(var + 1e-5f);
        o.y = fmaxf(fmaf(v.y, sc, bt.y - mu * sc), 0.f);
    }
    {
        float mu = s4.z * inv, var = q4.z * inv - mu * mu;
        float sc = gm.z * rsqrtf(var + 1e-5f);
        o.z = fmaxf(fmaf(v.z, sc, bt.z - mu * sc), 0.f);
    }
    {
        float mu = s4.w * inv, var = q4.w * inv - mu * mu;
        float sc = gm.w * rsqrtf(var + 1e-5f);
        o.w = fmaxf(fmaf(v.w, sc, bt.w - mu * sc), 0.f);
    }
    reinterpret_cast<float4*>(out)[idx] = o;
}

// ---------------------------------------------------------------------------
extern "C" void kernel_launch(void* const* d_in, const int* in_sizes, int n_in,
                              void* d_out, int out_size) {
    const float* h_states = (const float*)d_in[0];   // (1,B,H)
    const float* end_pos  = (const float*)d_in[1];   // (B,2)
    const float* rel_pos  = (const float*)d_in[2];   // (B,2)
    const float* scene    = (const float*)d_in[3];   // (S,P,2)
    const float* W_enc    = (const float*)d_in[4];   // (1,A)
    const float* b_enc    = (const float*)d_in[5];   // (A)
    const float* W_dec    = (const float*)d_in[6];   // (H,A)
    const float* b_dec    = (const float*)d_in[7];   // (A)
    const float* w_full   = (const float*)d_in[8];   // (A,1)
    // d_in[9]  = b_full (softmax-shift invariant -> unused)
    const float* W_out    = (const float*)d_in[10];  // (69,A)
    const float* b_out    = (const float*)d_in[11];  // (A)
    const float* W_mlp    = (const float*)d_in[12];  // (A,A)
    const float* b_mlp    = (const float*)d_in[13];  // (A)
    const float* gamma    = (const float*)d_in[14];  // (A)
    const float* beta     = (const float*)d_in[15];  // (A)
    float* out = (float*)d_out;

    prep_kernel<<<dim3(2, 256), 128>>>(h_states, W_dec, b_dec, b_enc);
    occwc_kernel<<<256 + 512, 256>>>(end_pos, scene, W_out, b_out, W_mlp);
    ectx_kernel<<<Bb, 128>>>(W_enc, w_full);
    y_kernel<<<dim3(2, 256), 128>>>(h_states, end_pos, rel_pos, b_mlp);
    finalize_kernel<<<(Bb * Aa / 4 + 255) / 256, 256>>>(gamma, beta, out);
}

// round 17
// speedup vs baseline: 1.1753x; 1.1753x over previous
#include <cuda_runtime.h>
#include <math.h>

// Problem constants
#define G2   64
#define Hh   64
#define Aa   1024
#define Ss   32
#define Pp   4096
#define Bb   2048
#define BMAX 512   // occupancy-count bucket range for ectx

typedef unsigned long long ull;

// -------- packed f32x2 helpers --------
__device__ __forceinline__ ull pk2(float lo, float hi) {
    ull r; asm("mov.b64 %0, {%1,%2};" : "=l"(r) : "f"(lo), "f"(hi)); return r;
}
__device__ __forceinline__ void upk2(ull v, float& lo, float& hi) {
    asm("mov.b64 {%0,%1}, %2;" : "=f"(lo), "=f"(hi) : "l"(v));
}
__device__ __forceinline__ ull ffma2(ull a, ull b, ull c) {
    ull d; asm("fma.rn.f32x2 %0, %1, %2, %3;" : "=l"(d) : "l"(a), "l"(b), "l"(c));
    return d;
}

// -------- device scratch (no allocations allowed) --------
__device__ float g_occ[Bb * G2];
__device__ float g_c[Bb * Aa];
__device__ float g_ctx[Bb];
__device__ float g_wc[70 * Aa];
__device__ float g_y[Bb * Aa];
__device__ float g_sum[Aa];
__device__ float g_sumsq[Aa];

// ---------------------------------------------------------------------------
// NODE 1: c = h@W_dec + b_dec + b_enc (4-col x 8-row register tiles),
//         PLUS zero g_wc/g_sum/g_sumsq.  grid (2, 256) x 128 thr.   [R16, measured]
__global__ __launch_bounds__(128) void prep_kernel(const float* __restrict__ h,
                                                   const float* __restrict__ Wd,
                                                   const float* __restrict__ bd,
                                                   const float* __restrict__ be) {
    {
        int gidx = (blockIdx.y * 2 + blockIdx.x) * 128 + threadIdx.x;
        const float4 z = make_float4(0.f, 0.f, 0.f, 0.f);
        if (gidx < 17920) {
            reinterpret_cast<float4*>(g_wc)[gidx] = z;
        } else if (gidx < 17920 + 256) {
            reinterpret_cast<float4*>(g_sum)[gidx - 17920] = z;
        } else if (gidx < 17920 + 512) {
            reinterpret_cast<float4*>(g_sumsq)[gidx - 17920 - 256] = z;
        }
    }

    int col0 = blockIdx.x * 512 + threadIdx.x * 4;
    int b0   = blockIdx.y * 8;
    __shared__ __align__(16) float hp[Hh * 8];   // hp[k*8 + bl]
    for (int idx = threadIdx.x; idx < 8 * Hh; idx += 128) {
        int k = idx >> 3, bl = idx & 7;
        hp[idx] = h[(b0 + bl) * Hh + k];
    }
    __syncthreads();

    ull acc[16];   // acc[c*4+p]: column c, row-pair p (rows 2p,2p+1)
#pragma unroll
    for (int i = 0; i < 16; i++) acc[i] = 0ull;

    const ulonglong2* hu = reinterpret_cast<const ulonglong2*>(hp);
#pragma unroll 4
    for (int k = 0; k < Hh; k += 4) {
        float4 wv[4];
#pragma unroll
        for (int i = 0; i < 4; i++)
            wv[i] = *reinterpret_cast<const float4*>(Wd + (size_t)(k + i) * Aa + col0);
#pragma unroll
        for (int rr = 0; rr < 4; rr++) {
            ulonglong2 u01 = hu[(k + rr) * 2];
            ulonglong2 u23 = hu[(k + rr) * 2 + 1];
            ull up[4] = { u01.x, u01.y, u23.x, u23.y };
            ull ww[4] = { pk2(wv[rr].x, wv[rr].x), pk2(wv[rr].y, wv[rr].y),
                          pk2(wv[rr].z, wv[rr].z), pk2(wv[rr].w, wv[rr].w) };
#pragma unroll
            for (int c = 0; c < 4; c++)
#pragma unroll
                for (int p = 0; p < 4; p++)
                    acc[c * 4 + p] = ffma2(up[p], ww[c], acc[c * 4 + p]);
        }
    }
    float4 bias;
    {
        float4 b1 = *reinterpret_cast<const float4*>(bd + col0);
        float4 b2 = *reinterpret_cast<const float4*>(be + col0);
        bias = make_float4(b1.x + b2.x, b1.y + b2.y, b1.z + b2.z, b1.w + b2.w);
    }
#pragma unroll
    for (int p = 0; p < 4; p++) {
        float v[2][4];
#pragma unroll
        for (int c = 0; c < 4; c++) {
            float lo, hi; upk2(acc[c * 4 + p], lo, hi);
            v[0][c] = lo; v[1][c] = hi;
        }
#pragma unroll
        for (int hh = 0; hh < 2; hh++) {
            float4 o = make_float4(v[hh][0] + bias.x, v[hh][1] + bias.y,
                                   v[hh][2] + bias.z, v[hh][3] + bias.w);
            *reinterpret_cast<float4*>(g_c + (size_t)(b0 + 2 * p + hh) * Aa + col0) = o;
        }
    }
}

// ---------------------------------------------------------------------------
// NODE 2: fat kernel — blocks [0,256): occupancy (plain stores, own region);
//         [256,768): Wc atomics (needs g_wc zeroed by prep).   [R16, measured]
__global__ __launch_bounds__(256) void occwc_kernel(const float* __restrict__ end_pos,
                                                    const float* __restrict__ scene,
                                                    const float* __restrict__ Wo,
                                                    const float* __restrict__ bo,
                                                    const float* __restrict__ Wm) {
    if (blockIdx.x < 256) {
        int grp = blockIdx.x & 7;
        int s   = blockIdx.x >> 3;
        int pedbase = s * 64 + grp * 8;

        __shared__ int bins[8][G2];
        __shared__ float4 boxsh[8];
        for (int i = threadIdx.x; i < 8 * G2; i += 256) ((int*)bins)[i] = 0;
        if (threadIdx.x < 8) {
            float ex = end_pos[(pedbase + threadIdx.x) * 2 + 0];
            float ey = end_pos[(pedbase + threadIdx.x) * 2 + 1];
            boxsh[threadIdx.x] = make_float4(ex - 1.0f, ey + 1.0f, ex + 1.0f, ey - 1.0f);
        }
        __syncthreads();

        float4 bx[8];
#pragma unroll
        for (int j = 0; j < 8; j++) bx[j] = boxsh[j];

        const float2* sc = reinterpret_cast<const float2*>(scene) + (size_t)s * Pp;
        for (int p = threadIdx.x; p < Pp; p += 256) {
            float2 q = sc[p];
#pragma unroll
            for (int j = 0; j < 8; j++) {
                bool in = (q.x < bx[j].z) && (q.x > bx[j].x) &&
                          (q.y < bx[j].y) && (q.y > bx[j].w);
                if (in) {
                    float cx = floorf(((q.x - bx[j].x) / 2.0f) * 8.0f);
                    float cy = floorf(((bx[j].y - q.y) / 2.0f) * 8.0f);
                    int cell = (int)(cx + cy * 8.0f);
                    if (cell >= 0 && cell < G2) {
                        atomicAdd(&bins[j][cell], 1);
                    } else {
                        long flat = (long)(pedbase + j) * G2 + cell;
                        if (flat >= 0 && flat < (long)Bb * G2)
                            atomicAdd(&g_occ[flat], 1.0f);   // rare bleed, exact int adds
                    }
                }
            }
        }
        __syncthreads();
        // own region: plain store (no zeroing pass needed)
        for (int i = threadIdx.x; i < 8 * G2; i += 256)
            g_occ[pedbase * G2 + i] = (float)((int*)bins)[i];
    } else {
        int wcb = blockIdx.x - 256;          // 0..511
        int a   = (wcb & 3) * 256 + threadIdx.x;
        int r0  = ((wcb >> 2) & 3) * 18;
        int k0  = (wcb >> 4) * 32;
        __shared__ __align__(16) float ws[9 * 32 * 2];

        for (int idx = threadIdx.x; idx < 9 * 32; idx += 256) {
            int p = idx >> 5, k = idx & 31;
            int r = r0 + 2 * p;
            float v0 = 0.f, v1 = 0.f;
            if (r < 69)       v0 = Wo[r * Aa + k0 + k];
            else if (r == 69) v0 = bo[k0 + k];
            if (r + 1 < 69)       v1 = Wo[(r + 1) * Aa + k0 + k];
            else if (r + 1 == 69) v1 = bo[k0 + k];
            ws[idx * 2]     = v0;
            ws[idx * 2 + 1] = v1;
        }
        __syncthreads();

        ull acc[9];
#pragma unroll
        for (int p = 0; p < 9; p++) acc[p] = 0ull;

        const ulonglong2* wsu = reinterpret_cast<const ulonglong2*>(ws);
#pragma unroll 2
        for (int k = 0; k < 32; k += 2) {
            float w0 = Wm[(size_t)(k0 + k) * Aa + a];
            float w1 = Wm[(size_t)(k0 + k + 1) * Aa + a];
            ull ww0 = pk2(w0, w0), ww1 = pk2(w1, w1);
#pragma unroll
            for (int p = 0; p < 9; p++) {
                ulonglong2 v = wsu[p * 16 + (k >> 1)];
                acc[p] = ffma2(v.x, ww0, acc[p]);
                acc[p] = ffma2(v.y, ww1, acc[p]);
            }
        }
#pragma unroll
        for (int p = 0; p < 9; p++) {
            int r = r0 + 2 * p;
            float lo, hi; upk2(acc[p], lo, hi);
            if (r < 70)     atomicAdd(&g_wc[r * Aa + a], lo);
            if (r + 1 < 70) atomicAdd(&g_wc[(r + 1) * Aa + a], hi);
        }
    }
}

// ---------------------------------------------------------------------------
// NODE 3: ectx via activation-threshold bucketing.   [R14, measured]
__global__ __launch_bounds__(128) void ectx_kernel(const float* __restrict__ We,
                                                   const float* __restrict__ wf) {
    __shared__ float Ad[BMAX], Cd[BMAX];
    __shared__ float sA[128], sC[128];
    __shared__ float redm[4], reds[4], redc[4];

    const int b   = blockIdx.x;
    const int tid = threadIdx.x;
    const float* crow = g_c + (size_t)b * Aa;

    for (int i = tid; i < BMAX; i += 128) { Ad[i] = 0.f; Cd[i] = 0.f; }
    __syncthreads();

    float A0 = 0.f, C0 = 0.f;
    for (int a = tid; a < Aa; a += 128) {
        float we = We[a], w = wf[a], c = crow[a];
        float wewf = we * w, cwf = c * w;
        if (we > 0.f) {
            float tau = __fdividef(-c, we);          // active for t > tau
            if (tau < 0.f) { A0 += wewf; C0 += cwf; }
            else if (tau < (float)(BMAX - 1)) {
                int t0 = (int)tau + 1;
                atomicAdd(&Ad[t0], wewf);
                atomicAdd(&Cd[t0], cwf);
            }
        } else if (we < 0.f) {
            float tau = __fdividef(-c, we);          // active for t < tau
            if (tau >= (float)(BMAX - 1)) { A0 += wewf; C0 += cwf; }
            else if (tau > 0.f) {
                A0 += wewf; C0 += cwf;
                int t1 = (int)ceilf(tau);
                atomicAdd(&Ad[t1], -wewf);
                atomicAdd(&Cd[t1], -cwf);
            }
        } else if (c > 0.f) {
            C0 += cwf;
        }
    }
#pragma unroll
    for (int off = 16; off >= 1; off >>= 1) {
        A0 += __shfl_xor_sync(0xffffffffu, A0, off);
        C0 += __shfl_xor_sync(0xffffffffu, C0, off);
    }
    if ((tid & 31) == 0) { atomicAdd(&Ad[0], A0); atomicAdd(&Cd[0], C0); }
    __syncthreads();

    int base = tid * 4;
    float pa0 = Ad[base], pa1 = Ad[base + 1], pa2 = Ad[base + 2], pa3 = Ad[base + 3];
    float pc0 = Cd[base], pc1 = Cd[base + 1], pc2 = Cd[base + 2], pc3 = Cd[base + 3];
    pa1 += pa0; pa2 += pa1; pa3 += pa2;
    pc1 += pc0; pc2 += pc1; pc3 += pc2;
    sA[tid] = pa3; sC[tid] = pc3;
    __syncthreads();
    for (int off = 1; off < 128; off <<= 1) {
        float va = (tid >= off) ? sA[tid - off] : 0.f;
        float vc = (tid >= off) ? sC[tid - off] : 0.f;
        __syncthreads();
        sA[tid] += va; sC[tid] += vc;
        __syncthreads();
    }
    float offA = sA[tid] - pa3, offC = sC[tid] - pc3;
    Ad[base] = pa0 + offA; Ad[base + 1] = pa1 + offA;
    Ad[base + 2] = pa2 + offA; Ad[base + 3] = pa3 + offA;
    Cd[base] = pc0 + offC; Cd[base + 1] = pc1 + offC;
    Cd[base + 2] = pc2 + offC; Cd[base + 3] = pc3 + offC;
    __syncthreads();

    float e = -1e30f, ogv = 0.f;
    if (tid < G2) {
        ogv = g_occ[b * G2 + tid];
        int t = (int)ogv;
        if (t < BMAX) {
            e = Ad[t] * ogv + Cd[t];
        } else {
            e = 0.f;
            for (int a = 0; a < Aa; a++)
                e = fmaf(fmaxf(fmaf(ogv, We[a], crow[a]), 0.f), wf[a], e);
        }
    }
    int warp = tid >> 5;
    float m = e;
#pragma unroll
    for (int off = 16; off >= 1; off >>= 1)
        m = fmaxf(m, __shfl_xor_sync(0xffffffffu, m, off));
    if ((tid & 31) == 0) redm[warp] = m;
    __syncthreads();
    m = fmaxf(fmaxf(redm[0], redm[1]), fmaxf(redm[2], redm[3]));

    float ex = __expf(e - m);
    float s = ex, cx = ex * ogv;
#pragma unroll
    for (int off = 16; off >= 1; off >>= 1) {
        s  += __shfl_xor_sync(0xffffffffu, s, off);
        cx += __shfl_xor_sync(0xffffffffu, cx, off);
    }
    if ((tid & 31) == 0) { reds[warp] = s; redc[warp] = cx; }
    __syncthreads();
    if (tid == 0)
        g_ctx[b] = (redc[0] + redc[1] + redc[2] + redc[3]) /
                   (reds[0] + reds[1] + reds[2] + reds[3]);
}

// ---------------------------------------------------------------------------
// NODE 4: y = u@Wc + bias, stats atomics. 16-row tile, 1024 blocks,
//         4-deep weight prefetch.   [R12, measured 17.5us]
__global__ __launch_bounds__(128) void y_kernel(const float* __restrict__ h,
                                                const float* __restrict__ ep,
                                                const float* __restrict__ rp,
                                                const float* __restrict__ bm) {
    int a  = blockIdx.x * 128 + threadIdx.x;
    int b0 = blockIdx.y * 16;
    __shared__ __align__(16) float us[69 * 16];
    for (int idx = threadIdx.x; idx < 69 * 16; idx += 128) {
        int r = idx >> 4, bl = idx & 15;
        int b = b0 + bl;
        float v;
        if (r == 0)      v = g_ctx[b];
        else if (r < 65) v = h[b * Hh + (r - 1)];
        else if (r < 67) v = ep[b * 2 + (r - 65)];
        else             v = rp[b * 2 + (r - 67)];
        us[idx] = v;
    }
    __syncthreads();

    ull acc[8] = {0, 0, 0, 0, 0, 0, 0, 0};
    const ulonglong2* usu = reinterpret_cast<const ulonglong2*>(us);
    const float* wcol = g_wc + a;
    for (int r = 0; r < 68; r += 4) {
        float w0 = wcol[(r + 0) * Aa];
        float w1 = wcol[(r + 1) * Aa];
        float w2 = wcol[(r + 2) * Aa];
        float w3 = wcol[(r + 3) * Aa];
        ull wwv[4] = { pk2(w0, w0), pk2(w1, w1), pk2(w2, w2), pk2(w3, w3) };
#pragma unroll
        for (int rr = 0; rr < 4; rr++) {
#pragma unroll
            for (int jj = 0; jj < 4; jj++) {
                ulonglong2 v = usu[(r + rr) * 4 + jj];
                acc[2 * jj]     = ffma2(v.x, wwv[rr], acc[2 * jj]);
                acc[2 * jj + 1] = ffma2(v.y, wwv[rr], acc[2 * jj + 1]);
            }
        }
    }
    {
        float w = wcol[68 * Aa];
        ull ww = pk2(w, w);
#pragma unroll
        for (int jj = 0; jj < 4; jj++) {
            ulonglong2 v = usu[68 * 4 + jj];
            acc[2 * jj]     = ffma2(v.x, ww, acc[2 * jj]);
            acc[2 * jj + 1] = ffma2(v.y, ww, acc[2 * jj + 1]);
        }
    }
    float bias = wcol[69 * Aa] + bm[a];
    float s = 0.f, s2 = 0.f;
#pragma unroll
    for (int j = 0; j < 8; j++) {
        float lo, hi; upk2(acc[j], lo, hi);
        float v0 = lo + bias, v1 = hi + bias;
        g_y[(size_t)(b0 + 2 * j) * Aa + a]     = v0;
        g_y[(size_t)(b0 + 2 * j + 1) * Aa + a] = v1;
        s += v0 + v1;
        s2 = fmaf(v0, v0, s2);
        s2 = fmaf(v1, v1, s2);
    }
    atomicAdd(&g_sum[a], s);
    atomicAdd(&g_sumsq[a], s2);
}

// ---------------------------------------------------------------------------
// NODE 5: out = relu(layernorm_batchdim(y)), stats recomputed inline.
__global__ __launch_bounds__(256) void finalize_kernel(const float* __restrict__ gamma,
                                                       const float* __restrict__ beta,
                                                       float* __restrict__ out) {
    int idx = blockIdx.x * blockDim.x + threadIdx.x;
    const int n = Bb * Aa / 4;
    if (idx >= n) return;
    int a = (idx * 4) & (Aa - 1);
    float4 v  = reinterpret_cast<const float4*>(g_y)[idx];
    float4 s4 = *reinterpret_cast<const float4*>(&g_sum[a]);
    float4 q4 = *reinterpret_cast<const float4*>(&g_sumsq[a]);
    float4 gm = *reinterpret_cast<const float4*>(&gamma[a]);
    float4 bt = *reinterpret_cast<const float4*>(&beta[a]);
    const float inv = 1.0f / (float)Bb;
    float4 o;
    {
        float mu = s4.x * inv, var = q4.x * inv - mu * mu;
        float sc = gm.x * rsqrtf(var + 1e-5f);
        o.x = fmaxf(fmaf(v.x, sc, bt.x - mu * sc), 0.f);
    }
    {
        float mu = s4.y * inv, var = q4.y * inv - mu * mu;
        float sc = gm.y * rsqrtf(var + 1e-5f);
        o.y = fmaxf(fmaf(v.y, sc, bt.y - mu * sc), 0.f);
    }
    {
        float mu = s4.z * inv, var = q4.z * inv - mu * mu;
        float sc = gm.z * rsqrtf(var + 1e-5f);
        o.z = fmaxf(fmaf(v.z, sc, bt.z - mu * sc), 0.f);
    }
    {
        float mu = s4.w * inv, var = q4.w * inv - mu * mu;
        float sc = gm.w * rsqrtf(var + 1e-5f);
        o.w = fmaxf(fmaf(v.w, sc, bt.w - mu * sc), 0.f);
    }
    reinterpret_cast<float4*>(out)[idx] = o;
}

// ---------------------------------------------------------------------------
extern "C" void kernel_launch(void* const* d_in, const int* in_sizes, int n_in,
                              void* d_out, int out_size) {
    const float* h_states = (const float*)d_in[0];   // (1,B,H)
    const float* end_pos  = (const float*)d_in[1];   // (B,2)
    const float* rel_pos  = (const float*)d_in[2];   // (B,2)
    const float* scene    = (const float*)d_in[3];   // (S,P,2)
    const float* W_enc    = (const float*)d_in[4];   // (1,A)
    const float* b_enc    = (const float*)d_in[5];   // (A)
    const float* W_dec    = (const float*)d_in[6];   // (H,A)
    const float* b_dec    = (const float*)d_in[7];   // (A)
    const float* w_full   = (const float*)d_in[8];   // (A,1)
    // d_in[9]  = b_full (softmax-shift invariant -> unused)
    const float* W_out    = (const float*)d_in[10];  // (69,A)
    const float* b_out    = (const float*)d_in[11];  // (A)
    const float* W_mlp    = (const float*)d_in[12];  // (A,A)
    const float* b_mlp    = (const float*)d_in[13];  // (A)
    const float* gamma    = (const float*)d_in[14];  // (A)
    const float* beta     = (const float*)d_in[15];  // (A)
    float* out = (float*)d_out;

    prep_kernel<<<dim3(2, 256), 128>>>(h_states, W_dec, b_dec, b_enc);
    occwc_kernel<<<256 + 512, 256>>>(end_pos, scene, W_out, b_out, W_mlp);
    ectx_kernel<<<Bb, 128>>>(W_enc, w_full);
    y_kernel<<<dim3(Aa / 128, Bb / 16), 128>>>(h_states, end_pos, rel_pos, b_mlp);
    finalize_kernel<<<(Bb * Aa / 4 + 255) / 256, 256>>>(gamma, beta, out);
}